// round 1
// baseline (speedup 1.0000x reference)
#include <cuda_runtime.h>

#define NN 50000
#define EE 800000
#define HH 128
#define ED 16
#define SP 132
#define XP 264

// ---------------- scratch (device globals: no allocations allowed) ----------
__device__ int   g_is64;
__device__ int   g_src[EE];
__device__ int   g_dst[EE];
__device__ float g_A[NN * HH];     // h @ We1[0:128]
__device__ float g_B[NN * HH];     // h @ We1[128:256]
__device__ float g_agg[NN * HH];   // segment-sum of m

__device__ __forceinline__ float siluf(float v) {
    return __fdividef(v, 1.0f + __expf(-v));
}

// ---------------- index dtype detection + conversion ------------------------
__global__ void k_detect(const void* ei) {
    if (blockIdx.x == 0 && threadIdx.x == 0) {
        const int* p = (const int*)ei;
        int acc = 0;
        for (int i = 0; i < 64; i++) acc |= p[2 * i + 1];
        g_is64 = (acc == 0) ? 1 : 0;  // int64 values < 2^31 -> high words all 0
    }
}

__global__ void k_convert(const void* ei) {
    int e = blockIdx.x * blockDim.x + threadIdx.x;
    if (e >= EE) return;
    if (g_is64) {
        const long long* p = (const long long*)ei;
        g_src[e] = (int)p[e];
        g_dst[e] = (int)p[EE + e];
    } else {
        const int* p = (const int*)ei;
        g_src[e] = p[e];
        g_dst[e] = p[EE + e];
    }
}

// ---------------- init: zero agg, x_out = x ---------------------------------
__global__ void k_init(const float* __restrict__ x, float* __restrict__ outx) {
    for (int i = blockIdx.x * blockDim.x + threadIdx.x; i < NN * HH;
         i += gridDim.x * blockDim.x) {
        g_agg[i] = 0.0f;
        if (i < NN * 3) outx[i] = x[i];
    }
}

// ---------------- node pre-GEMM: A = h@We1[0:128], B = h@We1[128:256] -------
__global__ __launch_bounds__(256, 2) void k_node_pre(
    const float* __restrict__ h, const float* __restrict__ We1) {
    extern __shared__ float sm[];
    float* ht = sm;            // 64*SP
    float* wt = sm + 64 * SP;  // 16*SP
    int tid = threadIdx.x;
    int n0 = blockIdx.x * 64;

#pragma unroll
    for (int v = 0; v < 8; v++) {
        int idx = tid * 32 + v * 4;
        int r = idx >> 7, c = idx & 127;
        float4 val = make_float4(0.f, 0.f, 0.f, 0.f);
        if (n0 + r < NN) val = *(const float4*)&h[(n0 + r) * 128 + c];
        *(float4*)&ht[r * SP + c] = val;
    }
    int rg = tid >> 4, cg = tid & 15;
    int r0 = rg * 4, c0 = cg * 8;

    for (int half = 0; half < 2; half++) {
        const float* W = We1 + half * 128 * 128;
        float acc[4][8];
#pragma unroll
        for (int i = 0; i < 4; i++)
#pragma unroll
            for (int j = 0; j < 8; j++) acc[i][j] = 0.f;

        for (int k0 = 0; k0 < 128; k0 += 16) {
            __syncthreads();
            int lin = tid * 8;
            int row = lin >> 7, col = lin & 127;
            *(float4*)&wt[row * SP + col] = *(const float4*)&W[(k0 + row) * 128 + col];
            *(float4*)&wt[row * SP + col + 4] = *(const float4*)&W[(k0 + row) * 128 + col + 4];
            __syncthreads();
#pragma unroll
            for (int kk = 0; kk < 16; kk++) {
                float sv[4];
#pragma unroll
                for (int i = 0; i < 4; i++) sv[i] = ht[(r0 + i) * SP + k0 + kk];
                float4 w0 = *(float4*)&wt[kk * SP + c0];
                float4 w1 = *(float4*)&wt[kk * SP + c0 + 4];
                float wv[8] = {w0.x, w0.y, w0.z, w0.w, w1.x, w1.y, w1.z, w1.w};
#pragma unroll
                for (int i = 0; i < 4; i++)
#pragma unroll
                    for (int j = 0; j < 8; j++) acc[i][j] += sv[i] * wv[j];
            }
        }
        float* out = half ? g_B : g_A;
#pragma unroll
        for (int i = 0; i < 4; i++) {
            if (n0 + r0 + i < NN) {
                *(float4*)&out[(n0 + r0 + i) * 128 + c0] =
                    make_float4(acc[i][0], acc[i][1], acc[i][2], acc[i][3]);
                *(float4*)&out[(n0 + r0 + i) * 128 + c0 + 4] =
                    make_float4(acc[i][4], acc[i][5], acc[i][6], acc[i][7]);
            }
        }
    }
}

// ---------------- fused edge kernel -----------------------------------------
__global__ __launch_bounds__(256, 2) void k_edge(
    const float* __restrict__ x, const float* __restrict__ ea,
    const float* __restrict__ We1, const float* __restrict__ be1,
    const float* __restrict__ We2, const float* __restrict__ be2,
    const float* __restrict__ Wx1, const float* __restrict__ bx1,
    const float* __restrict__ Wx2, const float* __restrict__ bx2,
    float* __restrict__ outx) {
    extern __shared__ float sm[];
    float* s    = sm;                 // 64*SP
    float* mm   = s + 64 * SP;        // 64*SP
    float* wt   = mm + 64 * SP;       // 16*SP
    float* w1e  = wt + 16 * SP;       // 16*SP (We1 rows 256..271)
    float* be1s = w1e + 16 * SP;      // 128
    float* be2s = be1s + 128;
    float* bx1s = be2s + 128;
    float* wds  = bx1s + 128;         // We1 row 272 (dist)
    float* wx2s = wds + 128;
    float* sdist = wx2s + 128;        // 64
    float* sgx = sdist + 64;
    float* sgy = sgx + 64;
    float* sgz = sgy + 64;
    float* sgate = sgz + 64;
    float* sea = sgate + 64;          // 64*16
    int* ssrc = (int*)(sea + 64 * 16);
    int* sdst = ssrc + 64;

    int tid = threadIdx.x;
    int e0 = blockIdx.x * 64;

    if (tid < 128) {
        be1s[tid] = be1[tid];
        be2s[tid] = be2[tid];
        bx1s[tid] = bx1[tid];
        wds[tid] = We1[272 * 128 + tid];
        wx2s[tid] = Wx2[tid];
    }
    {
        int lin = tid * 8;
        int row = lin >> 7, col = lin & 127;
        *(float4*)&w1e[row * SP + col] = *(const float4*)&We1[(256 + row) * 128 + col];
        *(float4*)&w1e[row * SP + col + 4] = *(const float4*)&We1[(256 + row) * 128 + col + 4];
    }
    if (tid < 64) {
        int e = e0 + tid;
        int si = g_src[e], di = g_dst[e];
        ssrc[tid] = si;
        sdst[tid] = di;
        float dx = x[di * 3 + 0] - x[si * 3 + 0];
        float dy = x[di * 3 + 1] - x[si * 3 + 1];
        float dz = x[di * 3 + 2] - x[si * 3 + 2];
        float ss2 = dx * dx + dy * dy + dz * dz;
        sdist[tid] = sqrtf(ss2 + 1e-9f);
        float rn = __fdividef(1.0f, sqrtf(ss2) + 1e-9f);
        sgx[tid] = dx * rn;
        sgy[tid] = dy * rn;
        sgz[tid] = dz * rn;
        sgate[tid] = bx2[0];
    }
    {
        int e_l = tid >> 2, j0 = (tid & 3) * 4;
        *(float4*)&sea[e_l * 16 + j0] = *(const float4*)&ea[(e0 + e_l) * 16 + j0];
    }
    __syncthreads();

    // ---- phase 1: s = silu(A[src]+B[dst]+ea@We1e + dist*wd + be1) ----
    {
        int e_l = tid >> 2, q = tid & 3;
        int si = ssrc[e_l], di = sdst[e_l];
        float d = sdist[e_l];
        float eav[16];
#pragma unroll
        for (int j = 0; j < 16; j++) eav[j] = sea[e_l * 16 + j];
        const float4* A4 = (const float4*)g_A;
        const float4* B4 = (const float4*)g_B;
#pragma unroll
        for (int i = 0; i < 8; i++) {
            int c = i * 16 + q * 4;  // q*4 keeps smem accesses conflict-free
            float4 a = A4[si * 32 + i * 4 + q];
            float4 b = B4[di * 32 + i * 4 + q];
            float4 bb = *(const float4*)&be1s[c];
            float4 wd4 = *(const float4*)&wds[c];
            float av[4] = {a.x + b.x + bb.x + d * wd4.x, a.y + b.y + bb.y + d * wd4.y,
                           a.z + b.z + bb.z + d * wd4.z, a.w + b.w + bb.w + d * wd4.w};
#pragma unroll
            for (int j = 0; j < 16; j++) {
                float4 w = *(const float4*)&w1e[j * SP + c];
                av[0] += eav[j] * w.x;
                av[1] += eav[j] * w.y;
                av[2] += eav[j] * w.z;
                av[3] += eav[j] * w.w;
            }
            float4 o = make_float4(siluf(av[0]), siluf(av[1]), siluf(av[2]), siluf(av[3]));
            *(float4*)&s[e_l * SP + c] = o;
        }
    }

    int rg = tid >> 4, cg = tid & 15;
    int r0 = rg * 4, c0 = cg * 8;

    // ---- GEMM1: mm = s @ We2 + be2 ----
    {
        float acc[4][8];
#pragma unroll
        for (int i = 0; i < 4; i++)
#pragma unroll
            for (int j = 0; j < 8; j++) acc[i][j] = be2s[c0 + j];

        for (int k0 = 0; k0 < 128; k0 += 16) {
            __syncthreads();
            int lin = tid * 8;
            int row = lin >> 7, col = lin & 127;
            *(float4*)&wt[row * SP + col] = *(const float4*)&We2[(k0 + row) * 128 + col];
            *(float4*)&wt[row * SP + col + 4] = *(const float4*)&We2[(k0 + row) * 128 + col + 4];
            __syncthreads();
#pragma unroll
            for (int kk = 0; kk < 16; kk++) {
                float sv[4];
#pragma unroll
                for (int i = 0; i < 4; i++) sv[i] = s[(r0 + i) * SP + k0 + kk];
                float4 w0 = *(float4*)&wt[kk * SP + c0];
                float4 w1 = *(float4*)&wt[kk * SP + c0 + 4];
                float wv[8] = {w0.x, w0.y, w0.z, w0.w, w1.x, w1.y, w1.z, w1.w};
#pragma unroll
                for (int i = 0; i < 4; i++)
#pragma unroll
                    for (int j = 0; j < 8; j++) acc[i][j] += sv[i] * wv[j];
            }
        }
#pragma unroll
        for (int i = 0; i < 4; i++) {
            *(float4*)&mm[(r0 + i) * SP + c0] =
                make_float4(acc[i][0], acc[i][1], acc[i][2], acc[i][3]);
            *(float4*)&mm[(r0 + i) * SP + c0 + 4] =
                make_float4(acc[i][4], acc[i][5], acc[i][6], acc[i][7]);
        }
    }

    // ---- GEMM2: gate += silu(mm@Wx1+bx1) . wx2 ----
    {
        float acc[4][8];
#pragma unroll
        for (int i = 0; i < 4; i++)
#pragma unroll
            for (int j = 0; j < 8; j++) acc[i][j] = bx1s[c0 + j];

        for (int k0 = 0; k0 < 128; k0 += 16) {
            __syncthreads();  // first iter: also makes mm visible to all
            int lin = tid * 8;
            int row = lin >> 7, col = lin & 127;
            *(float4*)&wt[row * SP + col] = *(const float4*)&Wx1[(k0 + row) * 128 + col];
            *(float4*)&wt[row * SP + col + 4] = *(const float4*)&Wx1[(k0 + row) * 128 + col + 4];
            __syncthreads();
#pragma unroll
            for (int kk = 0; kk < 16; kk++) {
                float sv[4];
#pragma unroll
                for (int i = 0; i < 4; i++) sv[i] = mm[(r0 + i) * SP + k0 + kk];
                float4 w0 = *(float4*)&wt[kk * SP + c0];
                float4 w1 = *(float4*)&wt[kk * SP + c0 + 4];
                float wv[8] = {w0.x, w0.y, w0.z, w0.w, w1.x, w1.y, w1.z, w1.w};
#pragma unroll
                for (int i = 0; i < 4; i++)
#pragma unroll
                    for (int j = 0; j < 8; j++) acc[i][j] += sv[i] * wv[j];
            }
        }
#pragma unroll
        for (int i = 0; i < 4; i++) {
            float p = 0.f;
#pragma unroll
            for (int j = 0; j < 8; j++) p += siluf(acc[i][j]) * wx2s[c0 + j];
            atomicAdd(&sgate[r0 + i], p);
        }
    }
    __syncthreads();

    // ---- scatter: agg[dst] += m ; x_out[dst] += dir * gate ----
    {
        int e_l = tid >> 2, q = tid & 3;
        int di = sdst[e_l];
        float* dstp = &g_agg[di * 128 + q * 32];
#pragma unroll
        for (int i = 0; i < 8; i++) {
            float4 v = *(float4*)&mm[e_l * SP + q * 32 + i * 4];
            atomicAdd(dstp + i * 4 + 0, v.x);
            atomicAdd(dstp + i * 4 + 1, v.y);
            atomicAdd(dstp + i * 4 + 2, v.z);
            atomicAdd(dstp + i * 4 + 3, v.w);
        }
    }
    if (tid < 64) {
        float gte = sgate[tid];
        int di = sdst[tid];
        atomicAdd(&outx[di * 3 + 0], sgx[tid] * gte);
        atomicAdd(&outx[di * 3 + 1], sgy[tid] * gte);
        atomicAdd(&outx[di * 3 + 2], sgz[tid] * gte);
    }
}

// ---------------- node update: LN(h + phi_h([h,agg])) -----------------------
__global__ __launch_bounds__(256, 2) void k_node_upd(
    const float* __restrict__ h, const float* __restrict__ Wh1,
    const float* __restrict__ bh1, const float* __restrict__ Wh2,
    const float* __restrict__ bh2, const float* __restrict__ lng,
    const float* __restrict__ lnb, float* __restrict__ outh) {
    extern __shared__ float sm[];
    float* xt = sm;             // 64*XP  ([h | agg])
    float* tt = xt + 64 * XP;   // 64*SP
    float* wt = tt + 64 * SP;   // 16*SP
    float* bh1s = wt + 16 * SP;
    float* bh2s = bh1s + 128;
    float* lngs = bh2s + 128;
    float* lnbs = lngs + 128;
    float* ssum = lnbs + 128;   // 64
    float* ssq = ssum + 64;     // 64

    int tid = threadIdx.x;
    int n0 = blockIdx.x * 64;
    if (tid < 128) {
        bh1s[tid] = bh1[tid];
        bh2s[tid] = bh2[tid];
        lngs[tid] = lng[tid];
        lnbs[tid] = lnb[tid];
    }
    if (tid < 64) {
        ssum[tid] = 0.f;
        ssq[tid] = 0.f;
    }
#pragma unroll
    for (int v = 0; v < 16; v++) {
        int idx = tid * 64 + v * 4;
        int r = idx >> 8, c = idx & 255;
        float4 val = make_float4(0.f, 0.f, 0.f, 0.f);
        if (n0 + r < NN) {
            if (c < 128)
                val = *(const float4*)&h[(n0 + r) * 128 + c];
            else
                val = *(const float4*)&g_agg[(n0 + r) * 128 + (c - 128)];
        }
        *(float4*)&xt[r * XP + c] = val;
    }
    __syncthreads();

    int rg = tid >> 4, cg = tid & 15;
    int r0 = rg * 4, c0 = cg * 8;

    // GEMM1: tt = silu([h,agg]@Wh1 + bh1), K=256
    {
        float acc[4][8];
#pragma unroll
        for (int i = 0; i < 4; i++)
#pragma unroll
            for (int j = 0; j < 8; j++) acc[i][j] = bh1s[c0 + j];

        for (int k0 = 0; k0 < 256; k0 += 16) {
            __syncthreads();
            int lin = tid * 8;
            int row = lin >> 7, col = lin & 127;
            *(float4*)&wt[row * SP + col] = *(const float4*)&Wh1[(k0 + row) * 128 + col];
            *(float4*)&wt[row * SP + col + 4] = *(const float4*)&Wh1[(k0 + row) * 128 + col + 4];
            __syncthreads();
#pragma unroll
            for (int kk = 0; kk < 16; kk++) {
                float sv[4];
#pragma unroll
                for (int i = 0; i < 4; i++) sv[i] = xt[(r0 + i) * XP + k0 + kk];
                float4 w0 = *(float4*)&wt[kk * SP + c0];
                float4 w1 = *(float4*)&wt[kk * SP + c0 + 4];
                float wv[8] = {w0.x, w0.y, w0.z, w0.w, w1.x, w1.y, w1.z, w1.w};
#pragma unroll
                for (int i = 0; i < 4; i++)
#pragma unroll
                    for (int j = 0; j < 8; j++) acc[i][j] += sv[i] * wv[j];
            }
        }
#pragma unroll
        for (int i = 0; i < 4; i++) {
            *(float4*)&tt[(r0 + i) * SP + c0] =
                make_float4(siluf(acc[i][0]), siluf(acc[i][1]), siluf(acc[i][2]), siluf(acc[i][3]));
            *(float4*)&tt[(r0 + i) * SP + c0 + 4] =
                make_float4(siluf(acc[i][4]), siluf(acc[i][5]), siluf(acc[i][6]), siluf(acc[i][7]));
        }
    }

    // GEMM2: dh = tt@Wh2 + bh2, K=128
    float acc2[4][8];
    {
#pragma unroll
        for (int i = 0; i < 4; i++)
#pragma unroll
            for (int j = 0; j < 8; j++) acc2[i][j] = bh2s[c0 + j];

        for (int k0 = 0; k0 < 128; k0 += 16) {
            __syncthreads();
            int lin = tid * 8;
            int row = lin >> 7, col = lin & 127;
            *(float4*)&wt[row * SP + col] = *(const float4*)&Wh2[(k0 + row) * 128 + col];
            *(float4*)&wt[row * SP + col + 4] = *(const float4*)&Wh2[(k0 + row) * 128 + col + 4];
            __syncthreads();
#pragma unroll
            for (int kk = 0; kk < 16; kk++) {
                float sv[4];
#pragma unroll
                for (int i = 0; i < 4; i++) sv[i] = tt[(r0 + i) * SP + k0 + kk];
                float4 w0 = *(float4*)&wt[kk * SP + c0];
                float4 w1 = *(float4*)&wt[kk * SP + c0 + 4];
                float wv[8] = {w0.x, w0.y, w0.z, w0.w, w1.x, w1.y, w1.z, w1.w};
#pragma unroll
                for (int i = 0; i < 4; i++)
#pragma unroll
                    for (int j = 0; j < 8; j++) acc2[i][j] += sv[i] * wv[j];
            }
        }
    }

    // v = h + dh; row stats
#pragma unroll
    for (int i = 0; i < 4; i++) {
        float p = 0.f, p2 = 0.f;
#pragma unroll
        for (int j = 0; j < 8; j++) {
            float v = xt[(r0 + i) * XP + c0 + j] + acc2[i][j];
            p += v;
            p2 += v * v;
        }
        atomicAdd(&ssum[r0 + i], p);
        atomicAdd(&ssq[r0 + i], p2);
    }
    __syncthreads();
#pragma unroll
    for (int i = 0; i < 4; i++) {
        int n = n0 + r0 + i;
        if (n < NN) {
            float mean = ssum[r0 + i] * (1.0f / 128.0f);
            float var = ssq[r0 + i] * (1.0f / 128.0f) - mean * mean;
            float rstd = rsqrtf(var + 1e-5f);
            float o[8];
#pragma unroll
            for (int j = 0; j < 8; j++) {
                float v = xt[(r0 + i) * XP + c0 + j] + acc2[i][j];
                o[j] = (v - mean) * rstd * lngs[c0 + j] + lnbs[c0 + j];
            }
            *(float4*)&outh[n * 128 + c0] = make_float4(o[0], o[1], o[2], o[3]);
            *(float4*)&outh[n * 128 + c0 + 4] = make_float4(o[4], o[5], o[6], o[7]);
        }
    }
}

// ---------------- launcher ---------------------------------------------------
extern "C" void kernel_launch(void* const* d_in, const int* in_sizes, int n_in,
                              void* d_out, int out_size) {
    const float* h = (const float*)d_in[0];
    const float* x = (const float*)d_in[1];
    const void* ei = d_in[2];
    const float* ea = (const float*)d_in[3];
    const float* We1 = (const float*)d_in[4];
    const float* be1 = (const float*)d_in[5];
    const float* We2 = (const float*)d_in[6];
    const float* be2 = (const float*)d_in[7];
    const float* Wh1 = (const float*)d_in[8];
    const float* bh1 = (const float*)d_in[9];
    const float* Wh2 = (const float*)d_in[10];
    const float* bh2 = (const float*)d_in[11];
    const float* Wx1 = (const float*)d_in[12];
    const float* bx1 = (const float*)d_in[13];
    const float* Wx2 = (const float*)d_in[14];
    const float* bx2 = (const float*)d_in[15];
    const float* lng = (const float*)d_in[16];
    const float* lnb = (const float*)d_in[17];

    float* outh = (float*)d_out;
    float* outx = outh + (size_t)NN * HH;

    const int SMEM_EDGE = 92928;
    const int SMEM_UPD = 112384;
    const int SMEM_PRE = 42240;
    cudaFuncSetAttribute(k_edge, cudaFuncAttributeMaxDynamicSharedMemorySize, SMEM_EDGE);
    cudaFuncSetAttribute(k_node_upd, cudaFuncAttributeMaxDynamicSharedMemorySize, SMEM_UPD);
    cudaFuncSetAttribute(k_node_pre, cudaFuncAttributeMaxDynamicSharedMemorySize, SMEM_PRE);

    k_detect<<<1, 32>>>(ei);
    k_convert<<<(EE + 255) / 256, 256>>>(ei);
    k_init<<<1024, 256>>>(x, outx);
    k_node_pre<<<(NN + 63) / 64, 256, SMEM_PRE>>>(h, We1);
    k_edge<<<EE / 64, 256, SMEM_EDGE>>>(x, ea, We1, be1, We2, be2, Wx1, bx1, Wx2,
                                        bx2, outx);
    k_node_upd<<<(NN + 63) / 64, 256, SMEM_UPD>>>(h, Wh1, bh1, Wh2, bh2, lng, lnb,
                                                  outh);
}